// round 1
// baseline (speedup 1.0000x reference)
#include <cuda_runtime.h>
#include <cstdint>

// Problem constants (fixed by setup_inputs)
constexpr int   NROWS = 200000;
constexpr int   DDIM  = 64;     // P and C
constexpr int   ODIM  = 8;
constexpr long long X1_ELEMS   = (long long)ODIM * NROWS * DDIM;   // 102,400,000
constexpr long long DAGS_OFF   = X1_ELEMS;                          // 102,400,000
constexpr long long REG_OFF    = DAGS_OFF + (long long)ODIM * DDIM * DDIM; // 102,432,768

constexpr int TILE_N    = 256;
constexpr int THREADS   = 256;
constexpr int XS_STRIDE = 260;  // floats: 16B-aligned rows, avoids heavy bank conflicts
constexpr int XS_BYTES  = 64 * XS_STRIDE * 4;  // 66560

__device__ __forceinline__ unsigned long long fma2(unsigned long long a,
                                                   unsigned long long b,
                                                   unsigned long long c) {
    unsigned long long d;
    asm("fma.rn.f32x2 %0, %1, %2, %3;" : "=l"(d) : "l"(a), "l"(b), "l"(c));
    return d;
}

__device__ __forceinline__ unsigned long long dup2(float a) {
    unsigned long long d;
    unsigned int ai = __float_as_uint(a);
    asm("mov.b64 %0, {%1, %1};" : "=l"(d) : "r"(ai));
    return d;
}

// GEMM: x1[o,n,c] = sum_p X[n,p] * (dags[o,p,c] * W[o,p,c])
__global__ void __launch_bounds__(THREADS, 2)
gemm_kernel(const float* __restrict__ X,
            const float* __restrict__ dags,
            const float* __restrict__ W,
            float* __restrict__ out)
{
    extern __shared__ float Xs[];          // [64][XS_STRIDE]  (transposed: Xs[p][n_local])
    __shared__ float WMs[64 * 64];         // [p][c]

    const int o   = blockIdx.x;
    const int n0  = blockIdx.y * TILE_N;
    const int tid = threadIdx.x;

    // ---- Build WM = dags * W in shared (L2-hit loads, 16 floats/thread) ----
    {
        const float4* dg4 = reinterpret_cast<const float4*>(dags + (size_t)o * 64 * 64);
        const float4* w4  = reinterpret_cast<const float4*>(W    + (size_t)o * 64 * 64);
        float4* wm4 = reinterpret_cast<float4*>(WMs);
        #pragma unroll
        for (int i = 0; i < 4; i++) {
            int j = tid + THREADS * i;
            float4 d = dg4[j];
            float4 w = w4[j];
            wm4[j] = make_float4(d.x * w.x, d.y * w.y, d.z * w.z, d.w * w.w);
        }
    }

    // ---- Load X tile [TILE_N x 64], transposed into Xs[p][n_local] ----
    // 4096 float4 total; each thread loads 16 float4, fully coalesced.
    #pragma unroll
    for (int i = 0; i < 16; i++) {
        int j   = tid + THREADS * i;   // float4 index in tile
        int row = j >> 4;              // n_local
        int c4  = j & 15;              // which float4 within the 64-wide row
        int n   = n0 + row;
        float4 v;
        if (n < NROWS) v = reinterpret_cast<const float4*>(X)[(size_t)n * 16 + c4];
        else           v = make_float4(0.f, 0.f, 0.f, 0.f);
        int c = c4 * 4;
        Xs[(c + 0) * XS_STRIDE + row] = v.x;
        Xs[(c + 1) * XS_STRIDE + row] = v.y;
        Xs[(c + 2) * XS_STRIDE + row] = v.z;
        Xs[(c + 3) * XS_STRIDE + row] = v.w;
    }
    __syncthreads();

    const int trow = tid >> 3;   // 0..31  -> rows r0..r0+7
    const int tcol = tid & 7;    // 0..7   -> cols c0..c0+7
    const int r0 = trow * 8;
    const int c0 = tcol * 8;

    // acc[r][j] holds (c0+2j, c0+2j+1) packed fp32x2 for row r
    unsigned long long acc[8][4];
    #pragma unroll
    for (int r = 0; r < 8; r++)
        #pragma unroll
        for (int j = 0; j < 4; j++) acc[r][j] = 0ULL;

    #pragma unroll 8
    for (int k = 0; k < 64; k++) {
        // b: 8 consecutive c values = 4 natural f32x2 pairs (two LDS.128)
        ulonglong2 b01 = *reinterpret_cast<const ulonglong2*>(&WMs[k * 64 + c0]);
        ulonglong2 b23 = *reinterpret_cast<const ulonglong2*>(&WMs[k * 64 + c0 + 4]);
        unsigned long long b[4] = {b01.x, b01.y, b23.x, b23.y};

        // a: 8 consecutive rows (two LDS.128), each duplicated into both halves
        float4 av0 = *reinterpret_cast<const float4*>(&Xs[k * XS_STRIDE + r0]);
        float4 av1 = *reinterpret_cast<const float4*>(&Xs[k * XS_STRIDE + r0 + 4]);
        float a[8] = {av0.x, av0.y, av0.z, av0.w, av1.x, av1.y, av1.z, av1.w};

        #pragma unroll
        for (int r = 0; r < 8; r++) {
            unsigned long long ap = dup2(a[r]);
            #pragma unroll
            for (int j = 0; j < 4; j++)
                acc[r][j] = fma2(ap, b[j], acc[r][j]);
        }
    }

    // ---- Store: out[o][n][c0..c0+7] ----
    float* x1 = out + (size_t)o * NROWS * 64;
    #pragma unroll
    for (int r = 0; r < 8; r++) {
        int n = n0 + r0 + r;
        if (n < NROWS) {
            float4* dst = reinterpret_cast<float4*>(x1 + (size_t)n * 64 + c0);
            float2 p0 = *reinterpret_cast<float2*>(&acc[r][0]);
            float2 p1 = *reinterpret_cast<float2*>(&acc[r][1]);
            float2 p2 = *reinterpret_cast<float2*>(&acc[r][2]);
            float2 p3 = *reinterpret_cast<float2*>(&acc[r][3]);
            dst[0] = make_float4(p0.x, p0.y, p1.x, p1.y);
            dst[1] = make_float4(p2.x, p2.y, p3.x, p3.y);
        }
    }
}

// Copies dags into the output and computes reg[o] = 1e-3 * sum(W[o]^2)
__global__ void tail_kernel(const float* __restrict__ dags,
                            const float* __restrict__ W,
                            float* __restrict__ out)
{
    const int o   = blockIdx.x;
    const int tid = threadIdx.x;
    const float4* dg4 = reinterpret_cast<const float4*>(dags + (size_t)o * 4096);
    const float4* w4  = reinterpret_cast<const float4*>(W    + (size_t)o * 4096);
    float4* od4 = reinterpret_cast<float4*>(out + DAGS_OFF + (size_t)o * 4096);

    float s = 0.f;
    #pragma unroll
    for (int i = 0; i < 4; i++) {
        int j = tid + 256 * i;
        float4 d = dg4[j];
        od4[j] = d;
        float4 w = w4[j];
        s += w.x * w.x + w.y * w.y + w.z * w.z + w.w * w.w;
    }

    // warp reduce
    #pragma unroll
    for (int off = 16; off > 0; off >>= 1)
        s += __shfl_xor_sync(0xFFFFFFFFu, s, off);

    __shared__ float warpsum[8];
    if ((tid & 31) == 0) warpsum[tid >> 5] = s;
    __syncthreads();
    if (tid < 32) {
        float t = (tid < 8) ? warpsum[tid] : 0.f;
        #pragma unroll
        for (int off = 4; off > 0; off >>= 1)
            t += __shfl_xor_sync(0xFFFFFFFFu, t, off);
        if (tid == 0) out[REG_OFF + o] = 0.001f * t;
    }
}

extern "C" void kernel_launch(void* const* d_in, const int* in_sizes, int n_in,
                              void* d_out, int out_size)
{
    const float* X    = (const float*)d_in[0];
    const float* dags = (const float*)d_in[1];
    const float* W    = (const float*)d_in[2];
    float* out = (float*)d_out;

    static bool attr_set = false;
    if (!attr_set) {
        cudaFuncSetAttribute(gemm_kernel,
                             cudaFuncAttributeMaxDynamicSharedMemorySize, XS_BYTES);
        attr_set = true;
    }

    dim3 grid(ODIM, (NROWS + TILE_N - 1) / TILE_N);  // o fast dim -> X reuse in L2
    gemm_kernel<<<grid, THREADS, XS_BYTES>>>(X, dags, W, out);
    tail_kernel<<<ODIM, 256>>>(dags, W, out);
}

// round 3
// speedup vs baseline: 2.2599x; 2.2599x over previous
#include <cuda_runtime.h>
#include <cuda_bf16.h>
#include <cstdint>

// ---------------- problem constants ----------------
constexpr int   NROWS = 200000;
constexpr int   ODIM  = 8;
constexpr long long X1_ELEMS = (long long)ODIM * NROWS * 64;      // 102,400,000
constexpr long long DAGS_OFF = X1_ELEMS;
constexpr long long REG_OFF  = DAGS_OFF + (long long)ODIM * 64 * 64;

constexpr int TILE_M = 128;
constexpr int NTILES = (NROWS + TILE_M - 1) / TILE_M;             // 1563

// ---------------- smem layout (dynamic, SW128-swizzled tiles) ----------------
constexpr int OFF_AHI = 0;                  // 128 rows x 128 B (bf16 [row][p])
constexpr int OFF_ALO = OFF_AHI + 16384;
constexpr int OFF_BHI = OFF_ALO + 16384;    // 64 rows (c) x 128 B (bf16 [c][p])
constexpr int OFF_BLO = OFF_BHI + 8192;
constexpr int SMEM_BYTES = OFF_BLO + 8192;  // 49152

#define SWZ128(x) ((x) ^ (((x) >> 3) & 0x70))

// ---------------- global scratch (bf16 split of dags*W, [o][c][p]) ----------------
__device__ __nv_bfloat16 g_WMhi[ODIM * 64 * 64];
__device__ __nv_bfloat16 g_WMlo[ODIM * 64 * 64];

// ---------------- PTX helpers ----------------
__device__ __forceinline__ uint32_t smem_u32(const void* p) {
    uint32_t a;
    asm("{ .reg .u64 t; cvta.to.shared.u64 t, %1; cvt.u32.u64 %0, t; }" : "=r"(a) : "l"(p));
    return a;
}
__device__ __forceinline__ void ldm_x4(uint32_t addr, uint32_t* r) {
    asm volatile("ldmatrix.sync.aligned.m8n8.x4.shared.b16 {%0,%1,%2,%3}, [%4];"
                 : "=r"(r[0]), "=r"(r[1]), "=r"(r[2]), "=r"(r[3]) : "r"(addr));
}
__device__ __forceinline__ void ldm_x2(uint32_t addr, uint32_t* r) {
    asm volatile("ldmatrix.sync.aligned.m8n8.x2.shared.b16 {%0,%1}, [%2];"
                 : "=r"(r[0]), "=r"(r[1]) : "r"(addr));
}
__device__ __forceinline__ void mma_bf16(float* d, const uint32_t* a, const uint32_t* b) {
    asm volatile("mma.sync.aligned.m16n8k16.row.col.f32.bf16.bf16.f32 "
                 "{%0,%1,%2,%3}, {%4,%5,%6,%7}, {%8,%9}, {%0,%1,%2,%3};"
                 : "+f"(d[0]), "+f"(d[1]), "+f"(d[2]), "+f"(d[3])
                 : "r"(a[0]), "r"(a[1]), "r"(a[2]), "r"(a[3]), "r"(b[0]), "r"(b[1]));
}

// ---------------- prep: WM split + dags copy + reg ----------------
__global__ void prep_kernel(const float* __restrict__ dags,
                            const float* __restrict__ W,
                            float* __restrict__ out)
{
    const int o   = blockIdx.x;
    const int tid = threadIdx.x;
    const float* dg = dags + (size_t)o * 4096;
    const float* ww = W    + (size_t)o * 4096;
    float* od = out + DAGS_OFF + (size_t)o * 4096;

    float s = 0.f;
    #pragma unroll
    for (int i = 0; i < 16; i++) {
        int j = tid + 256 * i;           // j = p*64 + c
        float d = dg[j];
        float w = ww[j];
        od[j] = d;
        s += w * w;
        float wm = d * w;
        __nv_bfloat16 hi = __float2bfloat16(wm);
        float lo = wm - __bfloat162float(hi);
        int p = j >> 6, c = j & 63;
        int t = (o << 12) | (c << 6) | p;   // [o][c][p]
        g_WMhi[t] = hi;
        g_WMlo[t] = __float2bfloat16(lo);
    }
    #pragma unroll
    for (int off = 16; off > 0; off >>= 1) s += __shfl_xor_sync(0xFFFFFFFFu, s, off);
    __shared__ float ws[8];
    if ((tid & 31) == 0) ws[tid >> 5] = s;
    __syncthreads();
    if (tid < 32) {
        float t = (tid < 8) ? ws[tid] : 0.f;
        #pragma unroll
        for (int off = 4; off > 0; off >>= 1) t += __shfl_xor_sync(0xFFFFFFFFu, t, off);
        if (tid == 0) out[REG_OFF + o] = 0.001f * t;
    }
}

// ---------------- HMMA GEMM: x1[o,n,c] = sum_p X[n,p] * WM[o,p,c] ----------------
__global__ void __launch_bounds__(128, 4)
gemm_kernel(const float* __restrict__ X, float* __restrict__ out)
{
    extern __shared__ char smem[];
    const uint32_t sb  = smem_u32(smem);
    const int tid  = threadIdx.x;
    const int wid  = tid >> 5;
    const int lane = tid & 31;
    const int n0   = blockIdx.x * TILE_M;

    // ---- X tile -> bf16 hi/lo, SW128-swizzled smem [row][p] ----
    {
        const float2* X2 = reinterpret_cast<const float2*>(X);
        #pragma unroll
        for (int i = tid; i < 4096; i += 128) {
            int row = i >> 5, pp = i & 31;          // pp = pair of p
            int n = n0 + row;
            float2 v = (n < NROWS) ? X2[(size_t)n * 32 + pp] : make_float2(0.f, 0.f);
            __nv_bfloat16 h0 = __float2bfloat16(v.x);
            __nv_bfloat16 h1 = __float2bfloat16(v.y);
            __nv_bfloat16 g0 = __float2bfloat16(v.x - __bfloat162float(h0));
            __nv_bfloat16 g1 = __float2bfloat16(v.y - __bfloat162float(h1));
            uint32_t hp = (uint32_t)__bfloat16_as_ushort(h0) |
                          ((uint32_t)__bfloat16_as_ushort(h1) << 16);
            uint32_t lp = (uint32_t)__bfloat16_as_ushort(g0) |
                          ((uint32_t)__bfloat16_as_ushort(g1) << 16);
            uint32_t off = SWZ128((uint32_t)(row * 128 + pp * 4));
            *reinterpret_cast<uint32_t*>(smem + OFF_AHI + off) = hp;
            *reinterpret_cast<uint32_t*>(smem + OFF_ALO + off) = lp;
        }
    }
    __syncthreads();

    // ---- Preload A fragments for this warp's 32 rows (reused across all 8 o) ----
    // afrag[mt][ks][hilo][4] : m16k16 tiles, rows wid*32 + mt*16, k = ks*16
    uint32_t afrag[2][4][2][4];
    #pragma unroll
    for (int mt = 0; mt < 2; mt++) {
        #pragma unroll
        for (int ks = 0; ks < 4; ks++) {
            int r  = wid * 32 + mt * 16 + (lane & 15);
            int kb = ks * 32 + (lane >> 4) * 16;         // byte offset along p
            uint32_t off = SWZ128((uint32_t)(r * 128 + kb));
            ldm_x4(sb + OFF_AHI + off, afrag[mt][ks][0]);
            ldm_x4(sb + OFF_ALO + off, afrag[mt][ks][1]);
        }
    }

    // B ldmatrix address (per lane, fixed across o / nt via add of nt*8*128)
    const uint32_t b_off_base = (uint32_t)((lane & 7) * 128 + ((lane >> 3) & 1) * 16);

    for (int o = 0; o < 8; o++) {
        __syncthreads();   // previous iteration's B reads complete
        // ---- stage B(o): WMhi/WMlo [c][p], swizzled ----
        {
            const uint4* bh = reinterpret_cast<const uint4*>(g_WMhi + o * 4096);
            const uint4* bl = reinterpret_cast<const uint4*>(g_WMlo + o * 4096);
            #pragma unroll
            for (int i = tid; i < 512; i += 128) {
                int row = i >> 3, q = i & 7;
                uint32_t off = SWZ128((uint32_t)(row * 128 + q * 16));
                *reinterpret_cast<uint4*>(smem + OFF_BHI + off) = bh[i];
                *reinterpret_cast<uint4*>(smem + OFF_BLO + off) = bl[i];
            }
        }
        __syncthreads();

        float* x1 = out + (size_t)o * NROWS * 64;

        #pragma unroll
        for (int nt = 0; nt < 8; nt++) {
            float acc[2][4];
            #pragma unroll
            for (int mt = 0; mt < 2; mt++)
                #pragma unroll
                for (int j = 0; j < 4; j++) acc[mt][j] = 0.f;

            #pragma unroll
            for (int ks = 0; ks < 4; ks++) {
                uint32_t bhi[2], blo[2];
                uint32_t boff = SWZ128(b_off_base + (uint32_t)(nt * 8 * 128 + ks * 32));
                ldm_x2(sb + OFF_BHI + boff, bhi);
                ldm_x2(sb + OFF_BLO + boff, blo);
                #pragma unroll
                for (int mt = 0; mt < 2; mt++) {
                    mma_bf16(acc[mt], afrag[mt][ks][0], bhi);   // Ahi*Bhi
                    mma_bf16(acc[mt], afrag[mt][ks][1], bhi);   // Alo*Bhi
                    mma_bf16(acc[mt], afrag[mt][ks][0], blo);   // Ahi*Blo
                }
            }

            // ---- store: D m16n8 fragment -> out[o][n][c], 32B-aligned float2 ----
            #pragma unroll
            for (int mt = 0; mt < 2; mt++) {
                int row = n0 + wid * 32 + mt * 16 + (lane >> 2);
                int col = nt * 8 + (lane & 3) * 2;
                if (row < NROWS)
                    *reinterpret_cast<float2*>(x1 + (size_t)row * 64 + col) =
                        make_float2(acc[mt][0], acc[mt][1]);
                if (row + 8 < NROWS)
                    *reinterpret_cast<float2*>(x1 + (size_t)(row + 8) * 64 + col) =
                        make_float2(acc[mt][2], acc[mt][3]);
            }
        }
    }
}

// ---------------- launch ----------------
extern "C" void kernel_launch(void* const* d_in, const int* in_sizes, int n_in,
                              void* d_out, int out_size)
{
    const float* X    = (const float*)d_in[0];
    const float* dags = (const float*)d_in[1];
    const float* W    = (const float*)d_in[2];
    float* out = (float*)d_out;

    static bool attr_set = false;
    if (!attr_set) {
        cudaFuncSetAttribute(gemm_kernel,
                             cudaFuncAttributeMaxDynamicSharedMemorySize, SMEM_BYTES);
        attr_set = true;
    }

    prep_kernel<<<ODIM, 256>>>(dags, W, out);
    gemm_kernel<<<NTILES, 128, SMEM_BYTES>>>(X, out);
}